// round 4
// baseline (speedup 1.0000x reference)
#include <cuda_runtime.h>

// Problem constants
#define NB 16
#define CI 32
#define CO 32
#define HH 224
#define WW 224
#define TILE_H 8
#define TILE_W 32
#define GX 7     // 224 / TILE_W
#define GY 28    // 224 / TILE_H
#define NBLK (GX*GY*NB)   // 3136 conv blocks

// Scratch (no allocations allowed -> __device__ globals)
__device__ double g_part[NBLK * 64];     // per-block per-channel [sum(0..31), sumsq(32..63)]
__device__ float  g_scale[CO];
__device__ float  g_bias[CO];

// ---------------------------------------------------------------------------
// Packed f32x2 helpers (sm_103a FFMA2 — only reachable via PTX fma.rn.f32x2)
// ---------------------------------------------------------------------------
__device__ __forceinline__ unsigned long long pack2(float w) {
    unsigned long long r;
    asm("mov.b64 %0, {%1, %1};" : "=l"(r) : "f"(w));
    return r;
}
__device__ __forceinline__ void ffma2(unsigned long long& d,
                                      unsigned long long a,
                                      unsigned long long b) {
    asm("fma.rn.f32x2 %0, %1, %2, %3;" : "=l"(d) : "l"(a), "l"(b), "l"(d));
}
__device__ __forceinline__ float lo32(unsigned long long v) {
    return __uint_as_float((unsigned)v);
}
__device__ __forceinline__ float hi32(unsigned long long v) {
    return __uint_as_float((unsigned)(v >> 32));
}

// Shared layout (floats):
//   ws : [c*9+k][o]  -> 32ch*9tap*32oc = 9216
//   xsA: 16c x 10rows x 36cols (col j = x[w0+j-1], halo-aligned)   = 5760
//   xsS: 16c x 10rows x 32cols (col j = x[w0+j]  , shifted copy)   = 5120
#define WS_FLOATS   (CI * 9 * 32)
#define XSA_FLOATS  (16 * 10 * 36)
#define XSS_FLOATS  (16 * 10 * 32)
#define SMEM_FLOATS (WS_FLOATS + XSA_FLOATS + XSS_FLOATS)

// ---------------------------------------------------------------------------
// Conv: binarized-weight 3x3, pad 1, everything in packed f32x2 FFMA2.
// One block = (n, 8h x 32w) tile, all 32 output channels.
// Warp = 32 output channels at same h -> all x LDS are broadcasts.
// Channels staged in two halves of 16 to keep smem at 2 CTAs/SM.
// ---------------------------------------------------------------------------
__global__ __launch_bounds__(256, 2)
void conv_kernel(const float* __restrict__ x, const float* __restrict__ wgt,
                 float* __restrict__ out)
{
    extern __shared__ float smem[];
    float* ws  = smem;                          // 9216
    float* xsA = smem + WS_FLOATS;              // 5760
    float* xsS = smem + WS_FLOATS + XSA_FLOATS; // 5120
    __shared__ double sred[512];

    const int tid = threadIdx.x;
    const int o   = tid & 31;         // output channel
    const int hg  = tid >> 5;         // row within tile (0..7)
    const int w0  = blockIdx.x * TILE_W;
    const int h0  = blockIdx.y * TILE_H;
    const int n   = blockIdx.z;

    // Binarize weights into shared: ws[(c*9+k)*32 + o] = sign(wgt[o][c][k])
    for (int i = tid; i < WS_FLOATS; i += 256) {
        int oo = i & 31;
        int j  = i >> 5;               // c*9+k
        ws[i] = (wgt[oo * 288 + j] >= 0.0f) ? 1.0f : -1.0f;
    }

    unsigned long long acc[16];        // 32 outputs as 16 f32x2 pairs
#pragma unroll
    for (int i = 0; i < 16; i++) acc[i] = 0ull;

    for (int half = 0; half < 2; half++) {
        // ---- stage 16 channels into xsA (halo-aligned) and xsS (shift-1) ----
        __syncthreads();   // protect previous iteration's reads
        for (int i = tid; i < XSA_FLOATS; i += 256) {
            int c   = i / 360;
            int rem = i - c * 360;
            int rr  = rem / 36;
            int cc  = rem - rr * 36;
            int gh = h0 + rr - 1;
            int gw = w0 + cc - 1;
            float v = 0.0f;
            if (gh >= 0 && gh < HH && gw >= 0 && gw < WW)
                v = x[((n * CI + (half * 16 + c)) * HH + gh) * WW + gw];
            xsA[i] = v;
        }
        for (int i = tid; i < XSS_FLOATS; i += 256) {
            int c   = i >> 9;              // /320? no: 10*32=320 per channel
            c = i / 320;
            int rem = i - c * 320;
            int rr  = rem >> 5;
            int cc  = rem & 31;
            int gh = h0 + rr - 1;
            float v = 0.0f;
            if (gh >= 0 && gh < HH)
                v = x[((n * CI + (half * 16 + c)) * HH + gh) * WW + (w0 + cc)];
            xsS[i] = v;
        }
        __syncthreads();

#pragma unroll 1
        for (int cg = 0; cg < 16; cg++) {
            const int c = half * 16 + cg;
            // 9 packed weights {w,w}
            unsigned long long w2[9];
#pragma unroll
            for (int k = 0; k < 9; k++)
                w2[k] = pack2(ws[(c * 9 + k) * 32 + o]);

#pragma unroll
            for (int dy = 0; dy < 3; dy++) {
                const float* rowA = xsA + cg * 360 + (hg + dy) * 36;
                const float* rowS = xsS + cg * 320 + (hg + dy) * 32;
                const unsigned long long wA = w2[dy * 3 + 0];
                const unsigned long long wB = w2[dy * 3 + 1];
                const unsigned long long wC = w2[dy * 3 + 2];
#pragma unroll
                for (int q = 0; q < 4; q++) {
                    // pairs A[4q..4q+4] from aligned copy, S[4q..4q+3] from shifted
                    const ulonglong2* pa = (const ulonglong2*)(rowA + 8 * q);
                    const ulonglong2* ps = (const ulonglong2*)(rowS + 8 * q);
                    ulonglong2 a01 = pa[0];
                    ulonglong2 a23 = pa[1];
                    unsigned long long a4 = *(const unsigned long long*)(rowA + 8 * q + 8);
                    ulonglong2 s01 = ps[0];
                    ulonglong2 s23 = ps[1];

                    ffma2(acc[4*q+0], a01.x, wA);
                    ffma2(acc[4*q+0], s01.x, wB);
                    ffma2(acc[4*q+0], a01.y, wC);

                    ffma2(acc[4*q+1], a01.y, wA);
                    ffma2(acc[4*q+1], s01.y, wB);
                    ffma2(acc[4*q+1], a23.x, wC);

                    ffma2(acc[4*q+2], a23.x, wA);
                    ffma2(acc[4*q+2], s23.x, wB);
                    ffma2(acc[4*q+2], a23.y, wC);

                    ffma2(acc[4*q+3], a23.y, wA);
                    ffma2(acc[4*q+3], s23.y, wB);
                    ffma2(acc[4*q+3], a4,    wC);
                }
            }
        }
    }

    // Write conv output (contiguous 128B per thread, vectorized) + stats
    const int base = ((n * CO + o) * HH + (h0 + hg)) * WW + w0;
    float4* op = (float4*)&out[base];
    double s = 0.0, ssq = 0.0;
#pragma unroll
    for (int q = 0; q < 8; q++) {
        float4 t;
        t.x = lo32(acc[2*q+0]); t.y = hi32(acc[2*q+0]);
        t.z = lo32(acc[2*q+1]); t.w = hi32(acc[2*q+1]);
        op[q] = t;
        double vx = (double)t.x, vy = (double)t.y, vz = (double)t.z, vw = (double)t.w;
        s   += vx + vy + vz + vw;
        ssq += vx*vx + vy*vy + vz*vz + vw*vw;
    }
    sred[o * 8 + hg]       = s;
    sred[256 + o * 8 + hg] = ssq;
    __syncthreads();

    const int bflat = blockIdx.x + GX * (blockIdx.y + GY * blockIdx.z);
    if (tid < 64) {
        int cch   = tid & 31;
        int which = tid >> 5;           // 0 = sum, 1 = sumsq
        double a = 0.0;
#pragma unroll
        for (int j = 0; j < 8; j++)     // fixed order -> deterministic
            a += sred[which * 256 + cch * 8 + j];
        g_part[bflat * 64 + which * 32 + cch] = a;
    }
}

// ---------------------------------------------------------------------------
// Reduce per-block partials -> per-channel BN scale/bias (deterministic tree)
// ---------------------------------------------------------------------------
__global__ void reduce_kernel(const float* __restrict__ gamma,
                              const float* __restrict__ beta)
{
    const int c = blockIdx.x;     // 32 blocks
    const int t = threadIdx.x;    // 256 threads
    __shared__ double sh[512];

    double s = 0.0, ssq = 0.0;
    for (int b = t; b < NBLK; b += 256) {
        s   += g_part[b * 64 + c];
        ssq += g_part[b * 64 + 32 + c];
    }
    sh[t]       = s;
    sh[256 + t] = ssq;
    __syncthreads();
    for (int step = 128; step > 0; step >>= 1) {
        if (t < step) {
            sh[t]       += sh[t + step];
            sh[256 + t] += sh[256 + t + step];
        }
        __syncthreads();
    }
    if (t == 0) {
        const double Nc   = (double)NB * HH * WW;
        double mean = sh[0] / Nc;
        double var  = sh[256] / Nc - mean * mean;
        double inv  = 1.0 / sqrt(var + 1e-5);
        double sc   = (double)gamma[c] * inv;
        g_scale[c] = (float)sc;
        g_bias[c]  = (float)((double)beta[c] - mean * sc);
    }
}

// ---------------------------------------------------------------------------
// Finalize: BN affine + hardtanh + 2-bit quantize (round-half-even), in place.
// 6,422,528 float4s = exactly 25088 blocks x 256 threads.
// ---------------------------------------------------------------------------
__device__ __forceinline__ float qclamp(float v, float sc, float bi)
{
    float y = fmaf(v, sc, bi);
    y = fminf(fmaxf(y, -1.0f), 1.0f);
    return rintf(y * 2.0f) * 0.5f;
}

__global__ void finalize_kernel(float4* __restrict__ out)
{
    const unsigned i = blockIdx.x * 256u + threadIdx.x;   // < 6422528
    const int c = (int)((i / 12544u) & 31u);              // 12544 float4s per (n,c) plane
    const float sc = g_scale[c];
    const float bi = g_bias[c];
    float4 v = out[i];
    v.x = qclamp(v.x, sc, bi);
    v.y = qclamp(v.y, sc, bi);
    v.z = qclamp(v.z, sc, bi);
    v.w = qclamp(v.w, sc, bi);
    out[i] = v;
}

// ---------------------------------------------------------------------------
extern "C" void kernel_launch(void* const* d_in, const int* in_sizes, int n_in,
                              void* d_out, int out_size)
{
    const float* x     = (const float*)d_in[0];   // (16,32,224,224)
    const float* wgt   = (const float*)d_in[1];   // (32,32,3,3) OIHW
    const float* gamma = (const float*)d_in[2];   // (32,)
    const float* beta  = (const float*)d_in[3];   // (32,)
    float* out = (float*)d_out;                   // (16,32,224,224)

    const size_t shmem = (size_t)SMEM_FLOATS * sizeof(float);  // 80,384 B
    cudaFuncSetAttribute(conv_kernel, cudaFuncAttributeMaxDynamicSharedMemorySize, (int)shmem);

    conv_kernel<<<dim3(GX, GY, NB), 256, shmem>>>(x, wgt, out);
    reduce_kernel<<<32, 256>>>(gamma, beta);
    finalize_kernel<<<25088, 256>>>((float4*)d_out);
}

// round 6
// speedup vs baseline: 2.3507x; 2.3507x over previous
#include <cuda_runtime.h>
#include <cuda_bf16.h>
#include <cstdint>

#define NB 16
#define HH 224
#define WW 224
#define GX 7
#define GY 28
#define NBLK (GX*GY*NB)      // 3136
#define NELEM 25690112       // 16*32*224*224

__device__ __align__(16) __nv_bfloat16 g_s1[NELEM];
__device__ __align__(16) __nv_bfloat16 g_s2[NELEM];
__device__ __align__(16) __nv_bfloat16 g_s3[NELEM];
__device__ double g_part[NBLK * 64];
__device__ float  g_scale[32];
__device__ float  g_bias[32];

__device__ __forceinline__ uint32_t smem_u32(const void* p) {
    uint32_t a;
    asm("{ .reg .u64 t; cvta.to.shared.u64 t, %1; cvt.u32.u64 %0, t; }" : "=r"(a) : "l"(p));
    return a;
}
__device__ __forceinline__ void ldsm4(uint32_t* r, uint32_t addr) {
    asm volatile("ldmatrix.sync.aligned.m8n8.x4.shared.b16 {%0,%1,%2,%3}, [%4];"
        : "=r"(r[0]), "=r"(r[1]), "=r"(r[2]), "=r"(r[3]) : "r"(addr));
}
__device__ __forceinline__ void ldsm4t(uint32_t* r, uint32_t addr) {
    asm volatile("ldmatrix.sync.aligned.m8n8.x4.trans.shared.b16 {%0,%1,%2,%3}, [%4];"
        : "=r"(r[0]), "=r"(r[1]), "=r"(r[2]), "=r"(r[3]) : "r"(addr));
}
__device__ __forceinline__ void mma4(float* d, const uint32_t* a, uint32_t b0, uint32_t b1) {
    asm volatile("mma.sync.aligned.m16n8k16.row.col.f32.bf16.bf16.f32 "
        "{%0,%1,%2,%3}, {%4,%5,%6,%7}, {%8,%9}, {%0,%1,%2,%3};"
        : "+f"(d[0]), "+f"(d[1]), "+f"(d[2]), "+f"(d[3])
        : "r"(a[0]), "r"(a[1]), "r"(a[2]), "r"(a[3]), "r"(b0), "r"(b1));
}

// ---------------------------------------------------------------------------
// Pre-pass: NCHW fp32 -> 3 NHWC bf16 split planes (x = s1+s2+s3, err<=2^-27|x|)
// ---------------------------------------------------------------------------
__global__ __launch_bounds__(256)
void split_kernel(const float* __restrict__ x)
{
    __shared__ float sm[32 * 33];
    const int t = threadIdx.x, w0 = blockIdx.x * 32, h = blockIdx.y, n = blockIdx.z;
    {
        int c = t >> 3, j = t & 7;
        float4 v = *(const float4*)(x + (((size_t)(n * 32 + c) * 224 + h) * 224 + w0 + j * 4));
        sm[(j*4+0)*33+c] = v.x; sm[(j*4+1)*33+c] = v.y;
        sm[(j*4+2)*33+c] = v.z; sm[(j*4+3)*33+c] = v.w;
    }
    __syncthreads();
    int ww = t >> 3, jj = t & 7;
    size_t ob = ((size_t)((n * 224 + h) * 224) + (w0 + ww)) * 32 + jj * 4;
    unsigned short p1[4], p2[4], p3[4];
#pragma unroll
    for (int i = 0; i < 4; i++) {
        float v0 = sm[ww * 33 + jj * 4 + i];
        __nv_bfloat16 h1 = __float2bfloat16_rn(v0);
        float r1 = v0 - __bfloat162float(h1);
        __nv_bfloat16 h2 = __float2bfloat16_rn(r1);
        float r2 = r1 - __bfloat162float(h2);
        p1[i] = __bfloat16_as_ushort(h1);
        p2[i] = __bfloat16_as_ushort(h2);
        p3[i] = __bfloat16_as_ushort(__float2bfloat16_rn(r2));
    }
    *(uint2*)((unsigned short*)g_s1 + ob) =
        make_uint2((unsigned)p1[0] | ((unsigned)p1[1] << 16), (unsigned)p1[2] | ((unsigned)p1[3] << 16));
    *(uint2*)((unsigned short*)g_s2 + ob) =
        make_uint2((unsigned)p2[0] | ((unsigned)p2[1] << 16), (unsigned)p2[2] | ((unsigned)p2[3] << 16));
    *(uint2*)((unsigned short*)g_s3 + ob) =
        make_uint2((unsigned)p3[0] | ((unsigned)p3[1] << 16), (unsigned)p3[2] | ((unsigned)p3[3] << 16));
}

// ---------------------------------------------------------------------------
// Conv: HMMA (mma.sync m16n8k16 bf16->f32) implicit GEMM.
// CTA = (n, 8h x 32w) tile: M=256 positions, N=32 out-channels.
// Warp hh handles M rows [hh*32, hh*32+32) (one h row), all 32 N.
// A staged per split: 10x34 halo positions x 40 bf16 (80B pitch, conflict-free
// ldmatrix since gcd(5,8)=1). B = binarized weights, 288 k-rows x 40 bf16.
// K loop: 3 splits x 9 taps x 2 k16-chunks; 8 HMMA per chunk per warp.
// ---------------------------------------------------------------------------
__global__ __launch_bounds__(256, 2)
void conv_kernel(const float* __restrict__ wgt, float* __restrict__ out)
{
    extern __shared__ unsigned char dsm[];
    __nv_bfloat16* Asm = (__nv_bfloat16*)dsm;            // 340 pos * 40 bf16 = 27200 B
    __nv_bfloat16* Bsm = (__nv_bfloat16*)(dsm + 27200);  // 288 k  * 40 bf16 = 23040 B
    float* smt = (float*)dsm;                            // alias: 256 m * 36 f32 = 36864 B
    __shared__ double sred[512];

    const int tid = threadIdx.x;
    const int l   = tid & 31;
    const int hh  = tid >> 5;
    const int w0  = blockIdx.x * 32, h0 = blockIdx.y * 8, n = blockIdx.z;

    const uint32_t Abase = smem_u32(Asm);
    const uint32_t Bbase = smem_u32(Bsm);
    // ldmatrix lane offset: row-in-16 = (seg&1)*8 + (l&7), 16B-half = seg>>1
    const uint32_t laneoff = (uint32_t)(((((l >> 3) & 1) * 8) + (l & 7)) * 80 + (l >> 4) * 16);

    // Stage binarized weights: Bsm[k = tap*32+c][o], pitch 40 bf16
    for (int i = tid; i < 288 * 32; i += 256) {
        int k = i >> 5, o = i & 31;
        int tap = k >> 5, c = k & 31;
        Bsm[k * 40 + o] = __float2bfloat16_rn((wgt[o * 288 + c * 9 + tap] >= 0.0f) ? 1.0f : -1.0f);
    }

    float acc[2][4][4];
#pragma unroll
    for (int a = 0; a < 2; a++)
#pragma unroll
        for (int b = 0; b < 4; b++)
#pragma unroll
            for (int c = 0; c < 4; c++) acc[a][b][c] = 0.0f;

#pragma unroll 1
    for (int s = 0; s < 3; s++) {
        const __nv_bfloat16* plane = (s == 0) ? g_s1 : ((s == 1) ? g_s2 : g_s3);
        __syncthreads();   // protect previous split's Asm reads (and Bsm stage, 1st iter)
        // Stage A: 340 halo positions, 64B payload each (4 x 16B lanes)
        for (int i = tid; i < 1360; i += 256) {
            int pos = i >> 2, q = i & 3;
            int hr = pos / 34, hc = pos - hr * 34;
            int gh = h0 + hr - 1, gw = w0 + hc - 1;
            uint4 v = make_uint4(0u, 0u, 0u, 0u);
            if (gh >= 0 && gh < HH && gw >= 0 && gw < WW)
                v = *(const uint4*)(plane + (size_t)((n * 224 + gh) * 224 + gw) * 32 + q * 8);
            *(uint4*)((unsigned char*)Asm + pos * 80 + q * 16) = v;
        }
        __syncthreads();

#pragma unroll
        for (int tap = 0; tap < 9; tap++) {
            const int dy = tap / 3, dx = tap - (tap / 3) * 3;
#pragma unroll
            for (int ch = 0; ch < 2; ch++) {
                uint32_t A0[4], A1[4], Bf[8];
                uint32_t ap = Abase + (uint32_t)((((hh + dy) * 34 + dx) * 80) + ch * 32) + laneoff;
                ldsm4(A0, ap);
                ldsm4(A1, ap + 1280);            // +16 positions (mi=1)
                uint32_t bp = Bbase + (uint32_t)((tap * 32 + ch * 16) * 80) + laneoff;
                ldsm4t(Bf,     bp);              // n0-15 : {b0,b1 | b0,b1}
                ldsm4t(Bf + 4, bp + 32);         // n16-31
#pragma unroll
                for (int ni = 0; ni < 4; ni++) {
                    mma4(acc[0][ni], A0, Bf[ni * 2], Bf[ni * 2 + 1]);
                    mma4(acc[1][ni], A1, Bf[ni * 2], Bf[ni * 2 + 1]);
                }
            }
        }
    }

    // ---- epilogue: accums -> smt[m][o] (pitch 36), stats, coalesced store ----
    __syncthreads();   // done reading Asm/Bsm; smt aliases them
    {
        const int g = l >> 2, t4 = l & 3;
#pragma unroll
        for (int mi = 0; mi < 2; mi++) {
            int m0 = hh * 32 + mi * 16 + g;
#pragma unroll
            for (int ni = 0; ni < 4; ni++) {
                int o0 = ni * 8 + 2 * t4;
                smt[m0 * 36 + o0]           = acc[mi][ni][0];
                smt[m0 * 36 + o0 + 1]       = acc[mi][ni][1];
                smt[(m0 + 8) * 36 + o0]     = acc[mi][ni][2];
                smt[(m0 + 8) * 36 + o0 + 1] = acc[mi][ni][3];
            }
        }
    }
    __syncthreads();

    // BN stats: f32 inner (32 values), double outer (fixed order -> deterministic)
    {
        const int o = tid & 31, part = tid >> 5;
        float s = 0.0f, q = 0.0f;
#pragma unroll
        for (int m = part * 32; m < part * 32 + 32; m++) {
            float v = smt[m * 36 + o];
            s += v;
            q = fmaf(v, v, q);
        }
        sred[o * 8 + part]       = (double)s;
        sred[256 + o * 8 + part] = (double)q;
    }

    // Store: thread = position m; per o, warp lanes = 32 consecutive w (coalesced)
    {
        const int hhm = tid >> 5, wwm = tid & 31;
        float* obase = out + ((size_t)n * 32 * 224 + (size_t)(h0 + hhm)) * 224 + w0 + wwm;
#pragma unroll
        for (int j = 0; j < 8; j++) {
            float v0 = smt[tid * 36 + j * 4 + 0];
            float v1 = smt[tid * 36 + j * 4 + 1];
            float v2 = smt[tid * 36 + j * 4 + 2];
            float v3 = smt[tid * 36 + j * 4 + 3];
            obase[(size_t)(j * 4 + 0) * 224 * 224] = v0;
            obase[(size_t)(j * 4 + 1) * 224 * 224] = v1;
            obase[(size_t)(j * 4 + 2) * 224 * 224] = v2;
            obase[(size_t)(j * 4 + 3) * 224 * 224] = v3;
        }
    }
    __syncthreads();

    const int bflat = blockIdx.x + GX * (blockIdx.y + GY * blockIdx.z);
    if (tid < 64) {
        int cch = tid & 31, which = tid >> 5;
        double a = 0.0;
#pragma unroll
        for (int j = 0; j < 8; j++)
            a += sred[which * 256 + cch * 8 + j];
        g_part[bflat * 64 + which * 32 + cch] = a;
    }
}

// ---------------------------------------------------------------------------
__global__ void reduce_kernel(const float* __restrict__ gamma,
                              const float* __restrict__ beta)
{
    const int c = blockIdx.x, t = threadIdx.x;   // 32 blocks x 256 threads
    __shared__ double sh[512];
    double s = 0.0, q = 0.0;
    for (int b = t; b < NBLK; b += 256) {
        s += g_part[b * 64 + c];
        q += g_part[b * 64 + 32 + c];
    }
    sh[t] = s; sh[256 + t] = q;
    __syncthreads();
    for (int step = 128; step > 0; step >>= 1) {
        if (t < step) { sh[t] += sh[t + step]; sh[256 + t] += sh[256 + t + step]; }
        __syncthreads();
    }
    if (t == 0) {
        const double Nc = (double)NB * HH * WW;
        double mean = sh[0] / Nc;
        double var  = sh[256] / Nc - mean * mean;
        double inv  = 1.0 / sqrt(var + 1e-5);
        double sc   = (double)gamma[c] * inv;
        g_scale[c] = (float)sc;
        g_bias[c]  = (float)((double)beta[c] - mean * sc);
    }
}

// ---------------------------------------------------------------------------
__device__ __forceinline__ float qclamp(float v, float sc, float bi)
{
    float y = fmaf(v, sc, bi);
    y = fminf(fmaxf(y, -1.0f), 1.0f);
    return rintf(y * 2.0f) * 0.5f;
}

__global__ void finalize_kernel(float4* __restrict__ out)
{
    const unsigned i = blockIdx.x * 256u + threadIdx.x;   // < 6422528
    const int c = (int)((i / 12544u) & 31u);
    const float sc = g_scale[c], bi = g_bias[c];
    float4 v = out[i];
    v.x = qclamp(v.x, sc, bi); v.y = qclamp(v.y, sc, bi);
    v.z = qclamp(v.z, sc, bi); v.w = qclamp(v.w, sc, bi);
    out[i] = v;
}

// ---------------------------------------------------------------------------
extern "C" void kernel_launch(void* const* d_in, const int* in_sizes, int n_in,
                              void* d_out, int out_size)
{
    const float* x     = (const float*)d_in[0];
    const float* wgt   = (const float*)d_in[1];
    const float* gamma = (const float*)d_in[2];
    const float* beta  = (const float*)d_in[3];
    float* out = (float*)d_out;

    const int shmem = 50240;   // max(A 27200 + B 23040, smt 36864)
    cudaFuncSetAttribute(conv_kernel, cudaFuncAttributeMaxDynamicSharedMemorySize, shmem);

    split_kernel<<<dim3(7, 224, NB), 256>>>(x);
    conv_kernel<<<dim3(GX, GY, NB), 256, shmem>>>(wgt, out);
    reduce_kernel<<<32, 256>>>(gamma, beta);
    finalize_kernel<<<25088, 256>>>((float4*)d_out);
}